// round 17
// baseline (speedup 1.0000x reference)
#include <cuda_runtime.h>
#include <cuda_bf16.h>
#include <cstdint>
#include <math.h>

#define LC   2048
#define CINV 0.35355339059327373f   // 1/(2*sqrt(2))

// Transposed wavelet weights, bf16, ldmatrix layout: [which][k][o][72 bf16]
__device__ __align__(16) __nv_bfloat16 g_wt[2][(size_t)LC * 4608];
// (W_skip + I) bf16 hi/lo split, k-paired, stride-36 rows: [c][36]
__device__ __align__(16) unsigned g_wskh[2304];
__device__ __align__(16) unsigned g_wskl[2304];

// smem word offsets
#define XH2_W   0        // [128 rows][36]  x-hi bf16 k-pairs
#define XL2_W   4608     // x-lo
#define UVH_W   9216     // [32 rows][36]   uv-hi (rows 0-15 u, 16-31 v)
#define UVL_W   10368
#define WT_W    11520    // ph<=2: W_t [2][64 o][36]; ph>=3: Wh2 (2304) + Wl2 (2304)
#define CORR_W  16128    // [2][16 b][66]
#define BIAS_W  18240    // 64
#define SMEM_BYTES (18304 * 4)

__device__ __forceinline__ float gelu_tanh(float v) {
    float z = 0.7978845608028654f * (v + 0.044715f * v * v * v);
    float t;
    asm("tanh.approx.f32 %0, %1;" : "=f"(t) : "f"(z));
    return 0.5f * v * (1.0f + t);
}

__device__ __forceinline__ unsigned pack_bf16(float a, float b) {
    __nv_bfloat162 h = __float22bfloat162_rn(make_float2(a, b));
    return *reinterpret_cast<unsigned*>(&h);
}
__device__ __forceinline__ float2 unpack_bf16(unsigned u) {
    return __bfloat1622float2(*reinterpret_cast<__nv_bfloat162*>(&u));
}

__device__ __forceinline__ void mma_bf16(float* d, const unsigned* a, const unsigned* b) {
    asm("mma.sync.aligned.m16n8k16.row.col.f32.bf16.bf16.f32 "
        "{%0,%1,%2,%3}, {%4,%5,%6,%7}, {%8,%9}, {%0,%1,%2,%3};"
        : "+f"(d[0]), "+f"(d[1]), "+f"(d[2]), "+f"(d[3])
        : "r"(a[0]), "r"(a[1]), "r"(a[2]), "r"(a[3]), "r"(b[0]), "r"(b[1]));
}

__device__ __forceinline__ void ldmatrix_x4(unsigned* r, uint32_t addr) {
    asm volatile("ldmatrix.sync.aligned.m8n8.x4.shared.b16 {%0,%1,%2,%3}, [%4];"
        : "=r"(r[0]), "=r"(r[1]), "=r"(r[2]), "=r"(r[3]) : "r"(addr));
}

// ---------------------------------------------------------------------------
// Kernel 1: w[i][o][l] -> g_wt[which][l][o*72 + i] bf16 (ldmatrix layout).
// grid (64 lt, 2 it, 128 = which*64 + o), block (32, 8)
// ---------------------------------------------------------------------------
__global__ void transpose_w_kernel(const float* __restrict__ wA,
                                   const float* __restrict__ wD) {
    __shared__ float tile[32][33];
    const int o     = blockIdx.z & 63;
    const int which = blockIdx.z >> 6;
    const float* src = which ? wD : wA;
    __nv_bfloat16* dst = g_wt[which];
    int lbase = blockIdx.x * 32;
    int ibase = blockIdx.y * 32;
    int tx = threadIdx.x, ty = threadIdx.y;
#pragma unroll
    for (int r = 0; r < 32; r += 8)
        tile[ty + r][tx] = src[(size_t)(ibase + ty + r) * 131072 + o * 2048 + lbase + tx];
    __syncthreads();
#pragma unroll
    for (int r = 0; r < 32; r += 8)
        dst[(size_t)(lbase + ty + r) * 4608 + o * 72 + ibase + tx] =
            __float2bfloat16(tile[tx][ty + r]);
}

// ---------------------------------------------------------------------------
// Kernel 1b: precompute (W_skip + I) bf16 hi/lo split in ldmatrix layout.
// ---------------------------------------------------------------------------
__global__ void prep_wsk_kernel(const float* __restrict__ Ws) {
    int tid = threadIdx.x;   // 256
#pragma unroll
    for (int it = 0; it < 8; it++) {
        int idx = tid + it * 256;          // 0..2047 -> (kp, c)
        int c = idx & 63, kp = idx >> 6;
        float w0 = Ws[(2 * kp) * 64 + c] + ((2 * kp) == c ? 1.f : 0.f);
        float w1 = Ws[(2 * kp + 1) * 64 + c] + ((2 * kp + 1) == c ? 1.f : 0.f);
        unsigned h = pack_bf16(w0, w1);
        float2 hf = unpack_bf16(h);
        unsigned l = pack_bf16(w0 - hf.x, w1 - hf.y);
        g_wskh[c * 36 + kp] = h;
        g_wskl[c * 36 + kp] = l;
    }
}

// ---------------------------------------------------------------------------
// Kernel 2: fused; GEMM + corrections on mma.sync, 32x32 warp tiles.
// Grid 4096 = (k, half). 256 threads, 16 batches x 8 rows x 64 ch. 3 CTAs/SM.
// ---------------------------------------------------------------------------
__global__ __launch_bounds__(256, 3) void fused_kernel(
    const float* __restrict__ x, const float* __restrict__ bsk,
    float* __restrict__ out)
{
    extern __shared__ float sm[];
    unsigned* smw  = (unsigned*)sm;
    float*    corr = sm + CORR_W;
    float*    bias = sm + BIAS_W;

    const int k    = blockIdx.x >> 1;
    const int half = blockIdx.x & 1;
    const int tid  = threadIdx.x;
    const int bl   = tid >> 4;
    const int c4   = tid & 15;

    // ---- Phase 0a: W_t (already ldmatrix-layout) -> WT region ----
    {
        const uint4* wt0 = (const uint4*)(g_wt[0] + (size_t)k * 4608);
        const uint4* wt1 = (const uint4*)(g_wt[1] + (size_t)k * 4608);
        uint4* dstw = (uint4*)(smw + WT_W);
#pragma unroll
        for (int it = 0; it < 3; it++) {
            int i = tid + it * 256;
            if (i < 576) { dstw[i] = wt0[i]; dstw[576 + i] = wt1[i]; }
        }
    }
    if (tid < 64) bias[tid] = __ldg(bsk + tid);

    // ---- Phase 0b: x load -> bf16 hi/lo split + u/v -> bf16 hi/lo rows ----
    {
        const int b = half * 16 + bl;
        const float4* xg = (const float4*)(x + ((size_t)b * 16384
                                                + (size_t)k * 8) * 64) + c4;
        float4 e = make_float4(0.f, 0.f, 0.f, 0.f);
        float4 d = make_float4(0.f, 0.f, 0.f, 0.f);
#pragma unroll
        for (int j = 0; j < 8; j++) {
            float4 v = __ldg(xg + j * 16);
            unsigned h0 = pack_bf16(v.x, v.y);
            unsigned h1 = pack_bf16(v.z, v.w);
            float2 h0f = unpack_bf16(h0), h1f = unpack_bf16(h1);
            unsigned l0 = pack_bf16(v.x - h0f.x, v.y - h0f.y);
            unsigned l1 = pack_bf16(v.z - h1f.x, v.w - h1f.y);
            int base = (bl * 8 + j) * 36 + 2 * c4;
            *(uint2*)(smw + XH2_W + base) = make_uint2(h0, h1);
            *(uint2*)(smw + XL2_W + base) = make_uint2(l0, l1);
            if (j < 4) { e.x += v.x; e.y += v.y; e.z += v.z; e.w += v.w; }
            else       { d.x += v.x; d.y += v.y; d.z += v.z; d.w += v.w; }
        }
        float u0 = CINV * (e.x + d.x), u1 = CINV * (e.y + d.y);
        float u2 = CINV * (e.z + d.z), u3 = CINV * (e.w + d.w);
        float v0 = CINV * (e.x - d.x), v1 = CINV * (e.y - d.y);
        float v2 = CINV * (e.z - d.z), v3 = CINV * (e.w - d.w);
        unsigned uh0 = pack_bf16(u0, u1), uh1 = pack_bf16(u2, u3);
        unsigned vh0 = pack_bf16(v0, v1), vh1 = pack_bf16(v2, v3);
        float2 t0 = unpack_bf16(uh0), t1 = unpack_bf16(uh1);
        float2 s0 = unpack_bf16(vh0), s1 = unpack_bf16(vh1);
        unsigned ul0 = pack_bf16(u0 - t0.x, u1 - t0.y);
        unsigned ul1 = pack_bf16(u2 - t1.x, u3 - t1.y);
        unsigned vl0 = pack_bf16(v0 - s0.x, v1 - s0.y);
        unsigned vl1 = pack_bf16(v2 - s1.x, v3 - s1.y);
        int ru = bl * 36 + 2 * c4, rv = (16 + bl) * 36 + 2 * c4;
        *(uint2*)(smw + UVH_W + ru) = make_uint2(uh0, uh1);
        *(uint2*)(smw + UVL_W + ru) = make_uint2(ul0, ul1);
        *(uint2*)(smw + UVH_W + rv) = make_uint2(vh0, vh1);
        *(uint2*)(smw + UVL_W + rv) = make_uint2(vl0, vl1);
    }
    __syncthreads();

    // ---- Phase 2: corrections via mma; 4 warps, (rt, 32-col half) ----
    if (tid < 128) {
        const int w    = tid >> 5;
        const int lane = tid & 31;
        const int g    = lane >> 2;
        const int tig  = lane & 3;
        const int rt   = w & 1;              // 0: u / w_approx, 1: v / w_detail
        const int ch2  = w >> 1;             // cols 32*ch2 .. +31

        const int aoffw = (rt * 16 + (lane & 15)) * 36 + ((lane >> 4) << 2);
        const uint32_t aH = (uint32_t)__cvta_generic_to_shared(smw + UVH_W + aoffw);
        const uint32_t aL = aH + 1152 * 4;

        const int bcol  = 32 * ch2 + ((lane >> 4) << 3) + (lane & 7);
        const int boffw = bcol * 36 + (((lane >> 3) & 1) << 2);
        const uint32_t bW = (uint32_t)__cvta_generic_to_shared(
                                smw + WT_W + rt * 2304 + boffw);

        float dc[4][4] = {};
#pragma unroll
        for (int ks = 0; ks < 4; ks++) {
            unsigned ah[4], al[4];
            ldmatrix_x4(ah, aH + ks * 32);
            ldmatrix_x4(al, aL + ks * 32);
#pragma unroll
            for (int p = 0; p < 2; p++) {
                unsigned bw[4];
                ldmatrix_x4(bw, bW + p * 2304 + ks * 32);
                mma_bf16(dc[2 * p],     ah, bw);
                mma_bf16(dc[2 * p],     al, bw);
                mma_bf16(dc[2 * p + 1], ah, bw + 2);
                mma_bf16(dc[2 * p + 1], al, bw + 2);
            }
        }

#pragma unroll
        for (int nt = 0; nt < 4; nt++) {
            const int col  = 32 * ch2 + nt * 8 + 2 * tig;
            const int word = col >> 1;
            {
                const int row = rt * 16 + g;
                float2 uh = unpack_bf16(smw[UVH_W + row * 36 + word]);
                float2 ul = unpack_bf16(smw[UVL_W + row * 36 + word]);
                float2 cv;
                cv.x = CINV * (dc[nt][0] - (uh.x + ul.x));
                cv.y = CINV * (dc[nt][1] - (uh.y + ul.y));
                *(float2*)(corr + rt * 1056 + g * 66 + col) = cv;
            }
            {
                const int row = rt * 16 + g + 8;
                float2 uh = unpack_bf16(smw[UVH_W + row * 36 + word]);
                float2 ul = unpack_bf16(smw[UVL_W + row * 36 + word]);
                float2 cv;
                cv.x = CINV * (dc[nt][2] - (uh.x + ul.x));
                cv.y = CINV * (dc[nt][3] - (uh.y + ul.y));
                *(float2*)(corr + rt * 1056 + (g + 8) * 66 + col) = cv;
            }
        }
    }
    __syncthreads();   // W_t + uv dead

    // ---- Phase 3: copy precomputed Wh2/Wl2 into WT region ----
    {
        uint4* s = (uint4*)(smw + WT_W);
#pragma unroll
        for (int it = 0; it < 3; it++) {
            int i = tid + it * 256;
            if (i < 576) {
                s[i]       = ((const uint4*)g_wskh)[i];
                s[576 + i] = ((const uint4*)g_wskl)[i];
            }
        }
    }
    __syncthreads();

    // ---- Phase 4: main GEMM (3-term), 32x32 warp tiles ----
    {
        const int w    = tid >> 5;
        const int lane = tid & 31;
        const int g    = lane >> 2;
        const int tig  = lane & 3;
        const int rq   = w & 3;              // rows 32*rq (batches 4rq..4rq+3)
        const int ch   = w >> 2;             // cols 32*ch

        uint32_t aH[2], aL[2];
#pragma unroll
        for (int t = 0; t < 2; t++) {
            const int arow  = (4 * rq + 2 * t + ((lane >> 3) & 1)) * 8 + (lane & 7);
            const int aoffw = arow * 36 + ((lane >> 4) << 2);
            aH[t] = (uint32_t)__cvta_generic_to_shared(smw + XH2_W + aoffw);
            aL[t] = aH[t] + 4608 * 4;
        }
        const int bcol  = 32 * ch + ((lane >> 4) << 3) + (lane & 7);
        const int boffw = bcol * 36 + (((lane >> 3) & 1) << 2);
        const uint32_t bH = (uint32_t)__cvta_generic_to_shared(smw + WT_W + boffw);
        const uint32_t bL = bH + 2304 * 4;

        float dacc[2][4][4] = {};
#pragma unroll
        for (int ks = 0; ks < 4; ks++) {
            unsigned ah[2][4], al[2][4];
            ldmatrix_x4(ah[0], aH[0] + ks * 32);
            ldmatrix_x4(al[0], aL[0] + ks * 32);
            ldmatrix_x4(ah[1], aH[1] + ks * 32);
            ldmatrix_x4(al[1], aL[1] + ks * 32);
#pragma unroll
            for (int p = 0; p < 2; p++) {
                unsigned bh[4], blo[4];
                ldmatrix_x4(bh,  bH + p * 2304 + ks * 32);
                ldmatrix_x4(blo, bL + p * 2304 + ks * 32);
#pragma unroll
                for (int t = 0; t < 2; t++) {
                    mma_bf16(dacc[t][2 * p],     ah[t], bh);
                    mma_bf16(dacc[t][2 * p],     al[t], bh);
                    mma_bf16(dacc[t][2 * p],     ah[t], blo);
                    mma_bf16(dacc[t][2 * p + 1], ah[t], bh + 2);
                    mma_bf16(dacc[t][2 * p + 1], al[t], bh + 2);
                    mma_bf16(dacc[t][2 * p + 1], ah[t], blo + 2);
                }
            }
        }

        const float sgn = (g < 4) ? 1.f : -1.f;
#pragma unroll
        for (int t = 0; t < 2; t++) {
            const int blA = 4 * rq + 2 * t;          // local batch
            const int bA  = half * 16 + blA;
            float* opA = out + ((size_t)bA * 16384 + (size_t)k * 8 + g) * 64;
            float* opB = out + ((size_t)(bA + 1) * 16384 + (size_t)k * 8 + g) * 64;
            const float* cA0 = corr + blA * 66;
            const float* cD0 = corr + 1056 + blA * 66;
#pragma unroll
            for (int nt = 0; nt < 4; nt++) {
                const int c = 32 * ch + nt * 8 + 2 * tig;
                float2 bi = *(const float2*)(bias + c);
                float2 a1 = *(const float2*)(cA0 + c);
                float2 d1 = *(const float2*)(cD0 + c);
                float2 rv;
                rv.x = gelu_tanh(dacc[t][nt][0] + a1.x + sgn * d1.x + bi.x);
                rv.y = gelu_tanh(dacc[t][nt][1] + a1.y + sgn * d1.y + bi.y);
                *(float2*)(opA + c) = rv;
                float2 a2 = *(const float2*)(cA0 + 66 + c);
                float2 d2 = *(const float2*)(cD0 + 66 + c);
                rv.x = gelu_tanh(dacc[t][nt][2] + a2.x + sgn * d2.x + bi.x);
                rv.y = gelu_tanh(dacc[t][nt][3] + a2.y + sgn * d2.y + bi.y);
                *(float2*)(opB + c) = rv;
            }
        }
    }
}

extern "C" void kernel_launch(void* const* d_in, const int* in_sizes, int n_in,
                              void* d_out, int out_size) {
    const float* x  = (const float*)d_in[0];   // (32, 16384, 64)
    const float* wA = (const float*)d_in[1];   // (64, 64, 2048)
    const float* wD = (const float*)d_in[2];   // (64, 64, 2048)
    const float* Ws = (const float*)d_in[3];   // (64, 64)
    const float* bs = (const float*)d_in[4];   // (64,)
    float* out = (float*)d_out;

    cudaFuncSetAttribute(fused_kernel,
        cudaFuncAttributeMaxDynamicSharedMemorySize, SMEM_BYTES);

    dim3 tb(32, 8), tg(64, 2, 128);
    transpose_w_kernel<<<tg, tb>>>(wA, wD);
    prep_wsk_kernel<<<1, 256>>>(Ws);

    fused_kernel<<<2 * LC, 256, SMEM_BYTES>>>(x, bs, out);
}